// round 3
// baseline (speedup 1.0000x reference)
#include <cuda_runtime.h>

// Local contrast normalization, fused, f32x2-packed design.
// mean = conv(x,w); d = x-mean; var = conv(d*d,w);
// out = (var>0.25) ? d*rsqrt(var) : d.  Both convs SAME zero-pad, 9x9 Gaussian
// (separable, asymmetric center 4.5).

typedef unsigned long long u64;

static constexpr int HH = 512, WW = 512;
static constexpr int TY = 32, TX = 64;

static constexpr int SXC = 84;  // sxe/sxo: 24 rows x 80 used (quad 21 odd)
static constexpr int STC = 60;  // stTe/stTo: 36 rows x 48 used (quad 15 odd)
static constexpr int SDC = 76;  // sde/sdo: 20 rows x 72 used (quad 19 odd)
static constexpr int T2C = 44;  // st2Te/o: 32 rows x 40 used (quad 11 odd)

// 1-D normalized Gaussian taps (verified vs reference, rel < 2e-6)
#define K0 0.000381553f
#define K1 0.00549127f
#define K2 0.04057532f
#define K3 0.15392929f
#define K4 0.29981330f

__device__ __forceinline__ u64 pk(float lo, float hi) {
    u64 r; asm("mov.b64 %0, {%1,%2};" : "=l"(r) : "f"(lo), "f"(hi)); return r;
}
__device__ __forceinline__ void unpk(u64 v, float& lo, float& hi) {
    asm("mov.b64 {%0,%1}, %2;" : "=f"(lo), "=f"(hi) : "l"(v));
}
__device__ __forceinline__ u64 f2mul(u64 a, u64 b) {
    u64 d; asm("mul.rn.f32x2 %0, %1, %2;" : "=l"(d) : "l"(a), "l"(b)); return d;
}
__device__ __forceinline__ u64 f2fma(u64 a, u64 b, u64 c) {
    u64 d; asm("fma.rn.f32x2 %0, %1, %2, %3;" : "=l"(d) : "l"(a), "l"(b), "l"(c)); return d;
}

__device__ __forceinline__ void ld16(const float* __restrict__ p, float a[16]) {
    #pragma unroll
    for (int q = 0; q < 4; q++) {
        float4 f = ((const float4*)p)[q];
        a[4*q] = f.x; a[4*q+1] = f.y; a[4*q+2] = f.z; a[4*q+3] = f.w;
    }
}

// packed 9-tap conv: o[k] = sum_j kv[m(j)] (x) a[k+j], 8 packed outputs
__device__ __forceinline__ void conv9x8p(const u64 a[16], const u64 kv[5], u64 o[8]) {
    #pragma unroll
    for (int k = 0; k < 8; k++) {
        o[k] = f2mul(kv[0], a[k]);
        o[k] = f2fma(kv[1], a[k+1], o[k]);
        o[k] = f2fma(kv[2], a[k+2], o[k]);
        o[k] = f2fma(kv[3], a[k+3], o[k]);
        o[k] = f2fma(kv[4], a[k+4], o[k]);
        o[k] = f2fma(kv[4], a[k+5], o[k]);
        o[k] = f2fma(kv[3], a[k+6], o[k]);
        o[k] = f2fma(kv[2], a[k+7], o[k]);
        o[k] = f2fma(kv[1], a[k+8], o[k]);
    }
}

__global__ __launch_bounds__(256)
void lcn_kernel(const float* __restrict__ x, float* __restrict__ out) {
    __shared__ __align__(16) float sxe[24 * SXC], sxo[24 * SXC]; // x tile, even/odd rows
    __shared__ __align__(16) float sbe[36 * STC], sbo[36 * STC]; // stT (even/odd cols); reused as st2T
    __shared__ __align__(16) float sde[20 * SDC], sdo[20 * SDC]; // demeaned, even/odd rows

    const int tid = threadIdx.x;
    const int ox = blockIdx.x * TX;
    const int oy = blockIdx.y * TY;
    const long base = (long)blockIdx.z * (HH * WW);

    u64 kv[5];
    kv[0] = pk(K0, K0); kv[1] = pk(K1, K1); kv[2] = pk(K2, K2);
    kv[3] = pk(K3, K3); kv[4] = pk(K4, K4);
    const u64 neg1 = pk(-1.f, -1.f);

    // ---- stage 0: load x tile (48 rows x 80 cols, zero-padded) ----
    #pragma unroll 1
    for (int idx = tid; idx < 48 * 20; idx += 256) {
        int r = idx / 20, g = idx - r * 20;
        int gy = oy - 8 + r;
        int gx = ox - 8 + g * 4;
        float4 v = make_float4(0.f, 0.f, 0.f, 0.f);
        if ((unsigned)gy < (unsigned)HH && (unsigned)gx < (unsigned)WW)
            v = *(const float4*)(x + base + (long)gy * WW + gx);
        float* dst = (r & 1) ? sxo : sxe;
        *(float4*)(dst + (r >> 1) * SXC + g * 4) = v;
    }
    __syncthreads();

    // ---- stage 1: h-conv of x, row pairs -> stT (transposed, col-split) ----
    if (tid < 216) {
        int r = tid % 24;          // row pair (2r, 2r+1)
        int ch = tid / 24;         // 0..8, c0 = 8*ch
        int c0 = ch * 8;
        float A[16], B[16];
        ld16(sxe + r * SXC + c0, A);
        ld16(sxo + r * SXC + c0, B);
        u64 ap[16];
        #pragma unroll
        for (int t = 0; t < 16; t++) ap[t] = pk(A[t], B[t]);
        u64 op[8];
        conv9x8p(ap, kv, op);
        // stT col c = c0+k (gx = ox-4+c); buffer by c&1=k&1, row c>>1, offset 2r
        #pragma unroll
        for (int k = 0; k < 8; k++) {
            float* sb = (k & 1) ? sbo : sbe;
            *(u64*)(sb + (4 * ch + (k >> 1)) * STC + 2 * r) = op[k];
        }
    }
    __syncthreads();

    // ---- stage 2: v-conv -> mean; d = x - mean (masked), col pairs ----
    if (tid < 180) {
        int cb = tid % 36;         // stT col pair (2cb, 2cb+1); gx = ox-4+2cb (+1)
        int rb = tid / 36;         // 0..4, r0 = 8*rb
        int r0 = rb * 8;
        float A[16], B[16];
        ld16(sbe + cb * STC + r0, A);
        ld16(sbo + cb * STC + r0, B);
        u64 ap[16];
        #pragma unroll
        for (int t = 0; t < 16; t++) ap[t] = pk(A[t], B[t]);
        u64 op[8];
        conv9x8p(ap, kv, op);
        int gxa = ox - 4 + 2 * cb;
        u64 cm = pk(((unsigned)gxa < (unsigned)WW) ? 1.f : 0.f,
                    ((unsigned)(gxa + 1) < (unsigned)WW) ? 1.f : 0.f);
        #pragma unroll
        for (int k = 0; k < 8; k++) {
            // x pair at sx row r0+k+4, cols (2cb+4, 2cb+5)
            const float* sxb = (k & 1) ? sxo : sxe;
            u64 x2 = *(const u64*)(sxb + (4 * rb + 2 + (k >> 1)) * SXC + (2 * cb + 4));
            bool rowok = (unsigned)(oy - 4 + r0 + k) < (unsigned)HH;
            u64 m = rowok ? cm : 0ULL;
            u64 d = f2mul(f2fma(op[k], neg1, x2), m);   // (x - mean) * mask
            float* sdb = (k & 1) ? sdo : sde;
            *(u64*)(sdb + (4 * rb + (k >> 1)) * SDC + 2 * cb) = d;
        }
    }
    __syncthreads();

    // ---- stage 3: h-conv of d^2, row pairs -> st2T (transposed, col-split) ----
    if (tid < 160) {
        int r = tid % 20;          // sd row pair (2r, 2r+1)
        int ch = tid / 20;         // 0..7, c0 = 8*ch
        int c0 = ch * 8;
        float A[16], B[16];
        ld16(sde + r * SDC + c0, A);
        ld16(sdo + r * SDC + c0, B);
        u64 ap[16];
        #pragma unroll
        for (int t = 0; t < 16; t++) {
            ap[t] = pk(A[t], B[t]);
            ap[t] = f2mul(ap[t], ap[t]);
        }
        u64 op[8];
        conv9x8p(ap, kv, op);
        // st2T col c = c0+k (gx = ox+c); buffer by k&1, row 4ch+(k>>1), offset 2r
        #pragma unroll
        for (int k = 0; k < 8; k++) {
            float* sb = (k & 1) ? sbo : sbe;   // reuse stT space as st2T
            *(u64*)(sb + (4 * ch + (k >> 1)) * T2C + 2 * r) = op[k];
        }
    }
    __syncthreads();

    // ---- stage 4: v-conv -> var; finalize; STG.64 ----
    if (tid < 128) {
        int cb = tid % 32;         // out col pair (ox+2cb, +1)
        int rb = tid / 32;         // 0..3, r0 = 8*rb
        int r0 = rb * 8;
        float A[16], B[16];
        ld16(sbe + cb * T2C + r0, A);
        ld16(sbo + cb * T2C + r0, B);
        u64 ap[16];
        #pragma unroll
        for (int t = 0; t < 16; t++) ap[t] = pk(A[t], B[t]);
        u64 op[8];
        conv9x8p(ap, kv, op);
        #pragma unroll
        for (int k = 0; k < 8; k++) {
            const float* sdb = (k & 1) ? sdo : sde;
            u64 d2 = *(const u64*)(sdb + (4 * rb + 2 + (k >> 1)) * SDC + (2 * cb + 4));
            float v0, v1;
            unpk(op[k], v0, v1);
            float m0 = (v0 > 0.25f) ? rsqrtf(v0) : 1.0f;
            float m1 = (v1 > 0.25f) ? rsqrtf(v1) : 1.0f;
            u64 res = f2mul(d2, pk(m0, m1));
            *(u64*)(out + base + (long)(oy + r0 + k) * WW + (ox + 2 * cb)) = res;
        }
    }
}

extern "C" void kernel_launch(void* const* d_in, const int* in_sizes, int n_in,
                              void* d_out, int out_size) {
    const float* x = (const float*)d_in[0];
    float* out = (float*)d_out;
    int B = in_sizes[0] / (HH * WW);
    dim3 grid(WW / TX, HH / TY, B);
    lcn_kernel<<<grid, 256>>>(x, out);
}

// round 4
// speedup vs baseline: 1.1404x; 1.1404x over previous
#include <cuda_runtime.h>

// Local contrast normalization, fused, pair-interleaved f32x2 design.
// mean = conv9x9_gauss(x); d = x - mean; var = conv9x9_gauss(d*d);
// out = (var > 0.25) ? d * rsqrt(var) : d.   SAME zero-pad, separable kernel,
// taps u[i] = exp(-(i-4.5)^2/3)/S (asymmetric center).

typedef unsigned long long u64;
typedef ulonglong2 u64x2;

static constexpr int HH = 512, WW = 512;
static constexpr int TY = 32, TX = 64;

// pitches chosen so lane-stride bytes = 16*odd -> conflict-free LDS/STS.128
static constexpr int SXP = 164;  // sx: float, 24 row-pairs x 160 used (interleaved pairs)
static constexpr int STP = 50;   // stT: u64, 36 col-pairs x 48 y
static constexpr int SDP = 148;  // sd: float, 20 row-pairs x 144 used
static constexpr int T2P = 42;   // st2: u64, 32 col-pairs x 40 y (aliases stT)

#define K0 0.000381553f
#define K1 0.00549127f
#define K2 0.04057532f
#define K3 0.15392929f
#define K4 0.29981330f

union F2 { u64 v; float f[2]; };

__device__ __forceinline__ u64 pk(float a, float b) {
    F2 t; t.f[0] = a; t.f[1] = b; return t.v;
}
__device__ __forceinline__ u64 f2mul(u64 a, u64 b) {
    u64 d; asm("mul.rn.f32x2 %0, %1, %2;" : "=l"(d) : "l"(a), "l"(b)); return d;
}
__device__ __forceinline__ u64 f2fma(u64 a, u64 b, u64 c) {
    u64 d; asm("fma.rn.f32x2 %0, %1, %2, %3;" : "=l"(d) : "l"(a), "l"(b), "l"(c)); return d;
}

// packed 9-tap conv over u64 window a[], NOUT outputs
template<int NOUT>
__device__ __forceinline__ void convp(const u64* a, const u64 kv[5], u64* o) {
    #pragma unroll
    for (int k = 0; k < NOUT; k++) {
        u64 acc = f2mul(kv[0], a[k]);
        acc = f2fma(kv[1], a[k+1], acc);
        acc = f2fma(kv[2], a[k+2], acc);
        acc = f2fma(kv[3], a[k+3], acc);
        acc = f2fma(kv[4], a[k+4], acc);
        acc = f2fma(kv[4], a[k+5], acc);
        acc = f2fma(kv[3], a[k+6], acc);
        acc = f2fma(kv[2], a[k+7], acc);
        acc = f2fma(kv[1], a[k+8], acc);
        o[k] = acc;
    }
}

__global__ __launch_bounds__(256)
void lcn_kernel(const float* __restrict__ x, float* __restrict__ out) {
    // x tile rows oy-8..oy+39 (pairs), cols ox-8..ox+71 interleaved by row parity
    __shared__ __align__(16) float sxp[24 * SXP];
    // stT[colpair cp][y]: (t[y][2cp], t[y][2cp+1]); col c ~ gx=ox-4+c ; reused as st2
    __shared__ __align__(16) u64 sb[36 * STP];
    // sd[rowpair][2c+par]: d rows oy-4..oy+35, cols ox-4..ox+67
    __shared__ __align__(16) float sdp[20 * SDP];

    const int tid = threadIdx.x;
    const int ox = blockIdx.x * TX;
    const int oy = blockIdx.y * TY;
    const long base = (long)blockIdx.z * (HH * WW);

    u64 kv[5];
    kv[0] = pk(K0, K0); kv[1] = pk(K1, K1); kv[2] = pk(K2, K2);
    kv[3] = pk(K3, K3); kv[4] = pk(K4, K4);
    const u64 neg1 = pk(-1.f, -1.f);
    const bool interior = (ox != 0) && (ox != WW - TX) && (oy != 0) && (oy != HH - TY);

    // ---------------- stage 0: load x tile, row-pair interleaved ----------------
    if (tid < 240) {
        int cg = tid % 10;          // 8-col group
        int rp = tid / 10;          // row pair
        int gye = oy - 8 + 2 * rp;
        int gx0 = ox - 8 + 8 * cg;
        const float* re = x + base + (long)gye * WW + gx0;
        float4 z = make_float4(0.f, 0.f, 0.f, 0.f);
        float4 e0 = z, e1 = z, o0 = z, o1 = z;
        bool rE = (unsigned)gye < (unsigned)HH;
        bool rO = (unsigned)(gye + 1) < (unsigned)HH;
        bool cA = (unsigned)gx0 < (unsigned)WW;
        bool cB = (unsigned)(gx0 + 4) < (unsigned)WW;
        if (rE && cA) e0 = *(const float4*)(re);
        if (rE && cB) e1 = *(const float4*)(re + 4);
        if (rO && cA) o0 = *(const float4*)(re + WW);
        if (rO && cB) o1 = *(const float4*)(re + WW + 4);
        float* d0 = sxp + rp * SXP + 16 * cg;
        ((float4*)d0)[0] = make_float4(e0.x, o0.x, e0.y, o0.y);
        ((float4*)d0)[1] = make_float4(e0.z, o0.z, e0.w, o0.w);
        ((float4*)d0)[2] = make_float4(e1.x, o1.x, e1.y, o1.y);
        ((float4*)d0)[3] = make_float4(e1.z, o1.z, e1.w, o1.w);
    }
    __syncthreads();

    // ---------------- stage 1: h-conv of x (y-pairs) -> stT (c-pairs) ----------------
    if (tid < 216) {
        int r = tid % 24;           // row pair (2r, 2r+1)
        int ch = tid / 24;          // col chunk, c0 = 8*ch (t-cols c0..c0+7)
        int c0 = 8 * ch;
        u64 ap[16];
        const u64x2* p = (const u64x2*)(sxp + r * SXP + 2 * c0);
        #pragma unroll
        for (int q = 0; q < 8; q++) { u64x2 v = p[q]; ap[2*q] = v.x; ap[2*q+1] = v.y; }
        u64 op[8];
        convp<8>(ap, kv, op);
        #pragma unroll
        for (int m = 0; m < 4; m++) {
            F2 e, o; e.v = op[2*m]; o.v = op[2*m+1];
            u64x2 w; w.x = pk(e.f[0], o.f[0]); w.y = pk(e.f[1], o.f[1]);
            *(u64x2*)(sb + (4*ch + m) * STP + 2*r) = w;
        }
    }
    __syncthreads();

    // ---------------- stage 2: v-conv -> mean; d = (x - mean)*mask -> sd ----------------
    if (tid < 180) {
        int cp = tid % 36;          // t col-pair: cols (2cp, 2cp+1), gx = ox-4+2cp
        int rb = tid / 36;          // d-row block, y0 = 8*rb (d rows y0..y0+7)
        int y0 = 8 * rb;
        u64 ap[16];
        const u64x2* p = (const u64x2*)(sb + cp * STP + y0);
        #pragma unroll
        for (int q = 0; q < 8; q++) { u64x2 v = p[q]; ap[2*q] = v.x; ap[2*q+1] = v.y; }
        u64 op[8];
        convp<8>(ap, kv, op);

        if (interior) {
            #pragma unroll
            for (int m = 0; m < 4; m++) {
                F2 p0, p1; p0.v = op[2*m]; p1.v = op[2*m+1];
                u64 meanE = pk(p0.f[0], p1.f[0]);   // col 2cp, rows (y0+2m, +1)
                u64 meanO = pk(p0.f[1], p1.f[1]);   // col 2cp+1
                u64x2 xv = *(const u64x2*)(sxp + (4*rb + m + 2) * SXP + 4*cp + 8);
                u64x2 w;
                w.x = f2fma(meanE, neg1, xv.x);
                w.y = f2fma(meanO, neg1, xv.y);
                *(u64x2*)(sdp + (4*rb + m) * SDP + 4*cp) = w;
            }
        } else {
            int ce = ox - 4 + 2 * cp;
            float cE = ((unsigned)ce < (unsigned)WW) ? 1.f : 0.f;
            float cO = ((unsigned)(ce + 1) < (unsigned)WW) ? 1.f : 0.f;
            #pragma unroll
            for (int m = 0; m < 4; m++) {
                F2 p0, p1; p0.v = op[2*m]; p1.v = op[2*m+1];
                u64 meanE = pk(p0.f[0], p1.f[0]);
                u64 meanO = pk(p0.f[1], p1.f[1]);
                u64x2 xv = *(const u64x2*)(sxp + (4*rb + m + 2) * SXP + 4*cp + 8);
                int gy = oy - 4 + y0 + 2*m;
                float r0 = ((unsigned)gy < (unsigned)HH) ? 1.f : 0.f;
                float r1 = ((unsigned)(gy+1) < (unsigned)HH) ? 1.f : 0.f;
                u64x2 w;
                w.x = f2mul(f2fma(meanE, neg1, xv.x), pk(r0*cE, r1*cE));
                w.y = f2mul(f2fma(meanO, neg1, xv.y), pk(r0*cO, r1*cO));
                *(u64x2*)(sdp + (4*rb + m) * SDP + 4*cp) = w;
            }
        }
    }
    __syncthreads();

    // ---------------- stage 3: h-conv of d^2 (y-pairs) -> st2 (c-pairs) ----------------
    if (tid < 160) {
        int r = tid % 20;           // d row pair (2r, 2r+1)
        int ch = tid / 20;          // out col chunk, c0 = 8*ch (out cols c0..c0+7)
        int c0 = 8 * ch;
        u64 ap[16];
        const u64x2* p = (const u64x2*)(sdp + r * SDP + 2 * c0);
        #pragma unroll
        for (int q = 0; q < 8; q++) {
            u64x2 v = p[q];
            ap[2*q]   = f2mul(v.x, v.x);
            ap[2*q+1] = f2mul(v.y, v.y);
        }
        u64 op[8];
        convp<8>(ap, kv, op);
        #pragma unroll
        for (int m = 0; m < 4; m++) {
            F2 e, o; e.v = op[2*m]; o.v = op[2*m+1];
            u64x2 w; w.x = pk(e.f[0], o.f[0]); w.y = pk(e.f[1], o.f[1]);
            *(u64x2*)(sb + (4*ch + m) * T2P + 2*r) = w;   // reuse sb as st2
        }
    }
    __syncthreads();

    // ---------------- stage 4: v-conv -> var; finalize; STG.64 ----------------
    {
        int cp = tid & 31;          // out col pair: gx = ox + 2cp (+1)
        int rb = tid >> 5;          // 0..7, y0 = 4*rb (out rows oy+y0..oy+y0+3)
        int y0 = 4 * rb;
        u64 ap[12];
        const u64x2* p = (const u64x2*)(sb + cp * T2P + y0);
        #pragma unroll
        for (int q = 0; q < 6; q++) { u64x2 v = p[q]; ap[2*q] = v.x; ap[2*q+1] = v.y; }
        u64 op[4];
        convp<4>(ap, kv, op);
        #pragma unroll
        for (int m = 0; m < 2; m++) {
            // d pairs for rows (y0+2m, y0+2m+1), cols (2cp+4, 2cp+5) in d-space
            u64x2 dv = *(const u64x2*)(sdp + (2*rb + m + 2) * SDP + 4*cp + 8);
            F2 A, B, V0, V1;
            A.v = dv.x; B.v = dv.y;          // A: col e rows (r0,r1); B: col o
            V0.v = op[2*m]; V1.v = op[2*m+1]; // V0: row r0 cols (e,o); V1: row r1
            float m00 = (V0.f[0] > 0.25f) ? rsqrtf(V0.f[0]) : 1.f;
            float m01 = (V0.f[1] > 0.25f) ? rsqrtf(V0.f[1]) : 1.f;
            float m10 = (V1.f[0] > 0.25f) ? rsqrtf(V1.f[0]) : 1.f;
            float m11 = (V1.f[1] > 0.25f) ? rsqrtf(V1.f[1]) : 1.f;
            float2 r0 = make_float2(A.f[0] * m00, B.f[0] * m01);
            float2 r1 = make_float2(A.f[1] * m10, B.f[1] * m11);
            long o0 = base + (long)(oy + y0 + 2*m) * WW + (ox + 2*cp);
            *(float2*)(out + o0)      = r0;
            *(float2*)(out + o0 + WW) = r1;
        }
    }
}

extern "C" void kernel_launch(void* const* d_in, const int* in_sizes, int n_in,
                              void* d_out, int out_size) {
    const float* x = (const float*)d_in[0];
    float* out = (float*)d_out;
    int B = in_sizes[0] / (HH * WW);
    dim3 grid(WW / TX, HH / TY, B);
    lcn_kernel<<<grid, 256>>>(x, out);
}